// round 15
// baseline (speedup 1.0000x reference)
#include <cuda_runtime.h>
#include <cuda_fp16.h>
#include <math.h>
#include <stdint.h>

// ---------------------------------------------------------------------------
// fkopt_net round 15: round-13 structure (producers / mega L2+L3+L4 with
// dependency counters / separate FK) with B fragments loaded via ldmatrix.x4
// (addressing validated in round 9) instead of x2: 16 -> 12 LDSM per kk.
// ---------------------------------------------------------------------------

#define BATCH 16384
#define KDIM  1024
#define NEG_SLOPE 0.01f

__device__ __align__(1024) __half g_a0h[BATCH * KDIM];
__device__ __align__(1024) __half g_a0l[BATCH * KDIM];
__device__ __align__(1024) __half g_a1h[BATCH * KDIM];
__device__ __align__(1024) __half g_a1l[BATCH * KDIM];
__device__ __align__(1024) __half g_w2h[KDIM * KDIM];
__device__ __align__(1024) __half g_w2l[KDIM * KDIM];
__device__ __align__(1024) __half g_w3h[KDIM * KDIM];
__device__ __align__(1024) __half g_w3l[KDIM * KDIM];
__device__ __align__(1024) __half g_w4h[256 * KDIM];
__device__ __align__(1024) __half g_w4l[256 * KDIM];
__device__ __align__(1024) float g_joints[BATCH * 256];
__device__ int g_cnt2[128];
__device__ int g_cnt3[128];

// ---------------- PTX helpers ----------------------------------------------
__device__ __forceinline__ uint32_t smem_u32(const void* p) {
    uint32_t a;
    asm("{ .reg .u64 t; cvta.to.shared.u64 t, %1; cvt.u32.u64 %0, t; }"
        : "=r"(a) : "l"(p));
    return a;
}
__device__ __forceinline__ void mbar_init(uint32_t a, uint32_t c) {
    asm volatile("mbarrier.init.shared.b64 [%0], %1;" :: "r"(a), "r"(c) : "memory");
}
__device__ __forceinline__ void mbar_expect(uint32_t a, uint32_t tx) {
    asm volatile("mbarrier.arrive.expect_tx.shared.b64 _, [%0], %1;"
                 :: "r"(a), "r"(tx) : "memory");
}
__device__ __forceinline__ void mbar_arrive(uint32_t a) {
    asm volatile("mbarrier.arrive.shared.b64 _, [%0];" :: "r"(a) : "memory");
}
__device__ __forceinline__ void mbar_wait(uint32_t a, uint32_t ph) {
    asm volatile(
        "{\n\t.reg .pred P;\n\t"
        "WL_%=:\n\t"
        "mbarrier.try_wait.parity.acquire.cta.shared::cta.b64 P, [%0], %1, 0x989680;\n\t"
        "@P bra.uni WD_%=;\n\t"
        "bra.uni WL_%=;\n\t"
        "WD_%=:\n\t}"
        :: "r"(a), "r"(ph) : "memory");
}
__device__ __forceinline__ void bulk_g2s(uint32_t dst, const void* src,
                                         uint32_t bytes, uint32_t mbar) {
    asm volatile(
        "cp.async.bulk.shared::cluster.global.mbarrier::complete_tx::bytes "
        "[%0], [%1], %2, [%3];"
        :: "r"(dst), "l"(src), "r"(bytes), "r"(mbar) : "memory");
}
__device__ __forceinline__ void bulk_s2g(void* dst, uint32_t src, uint32_t bytes) {
    asm volatile(
        "cp.async.bulk.global.shared::cta.bulk_group [%0], [%1], %2;"
        :: "l"(dst), "r"(src), "r"(bytes) : "memory");
}

#define LDSM4(r, a)                                                              \
    asm volatile("ldmatrix.sync.aligned.m8n8.x4.shared.b16 {%0,%1,%2,%3}, [%4];" \
                 : "=r"((r)[0]), "=r"((r)[1]), "=r"((r)[2]), "=r"((r)[3])        \
                 : "r"(a))
#define MMA16816(d, a, b)                                                        \
    asm volatile("mma.sync.aligned.m16n8k16.row.col.f32.f16.f16.f32 "            \
                 "{%0,%1,%2,%3}, {%4,%5,%6,%7}, {%8,%9}, {%0,%1,%2,%3};"         \
                 : "+f"((d)[0]), "+f"((d)[1]), "+f"((d)[2]), "+f"((d)[3])        \
                 : "r"((a)[0]), "r"((a)[1]), "r"((a)[2]), "r"((a)[3]),           \
                   "r"((b)[0]), "r"((b)[1]))

// tile byte-offset swizzle: off = row*64 + col*2 (32 fp16 cols per row)
__device__ __forceinline__ uint32_t swz(uint32_t off) {
    return off ^ (((off >> 7) & 3u) << 4);
}
__device__ __forceinline__ void split_h(float v, __half& h, __half& l) {
    h = __float2half_rn(v);
    l = __float2half_rn(v - __half2float(h));
}
__device__ __forceinline__ uint32_t pack_h2(__half a, __half b) {
    return ((uint32_t)__half_as_ushort(b) << 16) | (uint32_t)__half_as_ushort(a);
}

// ---------------------------------------------------------------------------
// Fused producers + counter reset (validated round 13).
// ---------------------------------------------------------------------------
__global__ __launch_bounds__(256) void producers_kernel(
    const float* __restrict__ x,  const float* __restrict__ W1,
    const float* __restrict__ b1, const float* __restrict__ W2,
    const float* __restrict__ W3, const float* __restrict__ W4,
    __half* __restrict__ a0h, __half* __restrict__ a0l,
    __half* __restrict__ w2h, __half* __restrict__ w2l,
    __half* __restrict__ w3h, __half* __restrict__ w3l,
    __half* __restrict__ w4h, __half* __restrict__ w4l)
{
    const int b = blockIdx.x;
    if (b == 9344) {
        if (threadIdx.x < 128) {
            g_cnt2[threadIdx.x] = 0;
            g_cnt3[threadIdx.x] = 0;
        }
        return;
    }
    if (b < 8192) {
        int idx = b * 256 + threadIdx.x;
        int n0 = (idx & 127) * 8;
        int m  = idx >> 7;
        float x0 = __ldg(x + m * 3 + 0);
        float x1 = __ldg(x + m * 3 + 1);
        float x2 = __ldg(x + m * 3 + 2);

        float4 wa0 = *(const float4*)(W1 + n0);
        float4 wa1 = *(const float4*)(W1 + n0 + 4);
        float4 wb0 = *(const float4*)(W1 + 1024 + n0);
        float4 wb1 = *(const float4*)(W1 + 1024 + n0 + 4);
        float4 wc0 = *(const float4*)(W1 + 2048 + n0);
        float4 wc1 = *(const float4*)(W1 + 2048 + n0 + 4);
        float4 bb0 = *(const float4*)(b1 + n0);
        float4 bb1 = *(const float4*)(b1 + n0 + 4);

        float v[8];
        v[0] = bb0.x + x0 * wa0.x + x1 * wb0.x + x2 * wc0.x;
        v[1] = bb0.y + x0 * wa0.y + x1 * wb0.y + x2 * wc0.y;
        v[2] = bb0.z + x0 * wa0.z + x1 * wb0.z + x2 * wc0.z;
        v[3] = bb0.w + x0 * wa0.w + x1 * wb0.w + x2 * wc0.w;
        v[4] = bb1.x + x0 * wa1.x + x1 * wb1.x + x2 * wc1.x;
        v[5] = bb1.y + x0 * wa1.y + x1 * wb1.y + x2 * wc1.y;
        v[6] = bb1.z + x0 * wa1.z + x1 * wb1.z + x2 * wc1.z;
        v[7] = bb1.w + x0 * wa1.w + x1 * wb1.w + x2 * wc1.w;

        uint32_t hw[4], lw[4];
        #pragma unroll
        for (int p = 0; p < 4; p++) {
            float v0 = v[2 * p], v1 = v[2 * p + 1];
            v0 = (v0 >= 0.0f) ? v0 : NEG_SLOPE * v0;
            v1 = (v1 >= 0.0f) ? v1 : NEG_SLOPE * v1;
            __half h0, l0, h1, l1;
            split_h(v0, h0, l0); split_h(v1, h1, l1);
            hw[p] = pack_h2(h0, h1);
            lw[p] = pack_h2(l0, l1);
        }
        size_t tile = (size_t)(m >> 7) * 32 + (n0 >> 5);
        uint32_t off = swz((uint32_t)(m & 127) * 64 + (uint32_t)(n0 & 31) * 2);
        *(uint4*)((char*)a0h + tile * 8192 + off) = make_uint4(hw[0], hw[1], hw[2], hw[3]);
        *(uint4*)((char*)a0l + tile * 8192 + off) = make_uint4(lw[0], lw[1], lw[2], lw[3]);
    } else {
        const float* W;
        __half *Ohi, *Olo;
        int N, bb;
        if (b < 8704)      { W = W2; Ohi = w2h; Olo = w2l; N = 1024; bb = b - 8192; }
        else if (b < 9216) { W = W3; Ohi = w3h; Olo = w3l; N = 1024; bb = b - 8704; }
        else               { W = W4; Ohi = w4h; Olo = w4l; N = 256;  bb = b - 9216; }
        int idx = bb * 256 + threadIdx.x;
        int n  = idx % N;
        int k0 = (idx / N) * 8;
        uint32_t hw[4], lw[4];
        #pragma unroll
        for (int p = 0; p < 4; p++) {
            float v0 = __ldg(W + (size_t)(k0 + 2 * p) * N + n);
            float v1 = __ldg(W + (size_t)(k0 + 2 * p + 1) * N + n);
            __half h0, l0, h1, l1;
            split_h(v0, h0, l0); split_h(v1, h1, l1);
            hw[p] = pack_h2(h0, h1);
            lw[p] = pack_h2(l0, l1);
        }
        size_t tile = (size_t)(n >> 7) * 32 + (k0 >> 5);
        uint32_t off = swz((uint32_t)(n & 127) * 64 + (uint32_t)(k0 & 31) * 2);
        *(uint4*)((char*)Ohi + tile * 8192 + off) = make_uint4(hw[0], hw[1], hw[2], hw[3]);
        *(uint4*)((char*)Olo + tile * 8192 + off) = make_uint4(lw[0], lw[1], lw[2], lw[3]);
    }
}

// ---------------------------------------------------------------------------
// One GEMM tile (128x128, K=1024), fp16x3 mma.sync, 3-stage pipeline.
// B fragments via ldmatrix.x4 (round-9-validated addressing).
// ---------------------------------------------------------------------------
template <int MODE>
__device__ __forceinline__ void gemm_tile(
    const __half* __restrict__ Ahg, const __half* __restrict__ Alg,
    const __half* __restrict__ Bhg, const __half* __restrict__ Blg,
    const float* __restrict__ bias,
    __half* __restrict__ Ohi, __half* __restrict__ Olo,
    float* __restrict__ Of, int Ntot, int mb, int nb,
    volatile int* wait_cnt, int wait_target, int* sig,
    char* dsm)
{
    constexpr int NC = 32;
    constexpr uint32_t STAGE = 32768;
    __shared__ __align__(8) uint64_t bar_full[3], bar_empty[3];
    const uint32_t sbase = (smem_u32(dsm) + 1023) & ~1023u;

    const int tid = threadIdx.x, lane = tid & 31, wid = tid >> 5;
    const int wm = (wid & 1) * 64;
    const int wn = (wid >> 1) * 32;

    if (tid == 0) {
        for (int s = 0; s < 3; s++) {
            mbar_init(smem_u32(&bar_full[s]), 1);
            mbar_init(smem_u32(&bar_empty[s]), 8);
        }
    }
    __syncthreads();

    const char* Ah = (const char*)Ahg + (size_t)mb * 32 * 8192;
    const char* Al = (const char*)Alg + (size_t)mb * 32 * 8192;
    const char* Bh = (const char*)Bhg + (size_t)nb * 32 * 8192;
    const char* Bl = (const char*)Blg + (size_t)nb * 32 * 8192;

    if (tid == 0) {
        if (wait_cnt) {
            while (*wait_cnt < wait_target) __nanosleep(64);
            __threadfence();
        }
        #pragma unroll
        for (int c = 0; c < 2; c++) {
            uint32_t fb = smem_u32(&bar_full[c]);
            mbar_expect(fb, STAGE);
            uint32_t d = sbase + c * STAGE;
            bulk_g2s(d,         Ah + (size_t)c * 8192, 8192, fb);
            bulk_g2s(d + 8192,  Al + (size_t)c * 8192, 8192, fb);
            bulk_g2s(d + 16384, Bh + (size_t)c * 8192, 8192, fb);
            bulk_g2s(d + 24576, Bl + (size_t)c * 8192, 8192, fb);
        }
    }

    // A ldmatrix addressing (unchanged)
    const int rowA = wm + (lane & 15);
    const uint32_t xa = (rowA >> 1) & 3;
    const uint32_t offA = (uint32_t)rowA * 64;
    const uint32_t cA[2] = { (((uint32_t)(lane >> 4) + 0) ^ xa) * 16,
                             (((uint32_t)(lane >> 4) + 2) ^ xa) * 16 };

    // B ldmatrix.x4 addressing (validated round 9):
    // g = lane>>3: g0 -> (ni even, k-lo), g1 -> (ni even, k-hi),
    //              g2 -> (ni odd,  k-lo), g3 -> (ni odd,  k-hi)
    const int g = lane >> 3;
    uint32_t addrB[2][2];   // [npair][kk] byte offset within a B tile
    #pragma unroll
    for (int p = 0; p < 2; p++) {
        int rowB = wn + p * 16 + ((g >> 1) << 3) + (lane & 7);
        uint32_t xb = ((uint32_t)rowB >> 1) & 3;
        #pragma unroll
        for (int kk = 0; kk < 2; kk++) {
            uint32_t quad = (uint32_t)(g & 1) + 2u * kk;
            addrB[p][kk] = (uint32_t)rowB * 64 + ((quad ^ xb) << 4);
        }
    }

    float acc[4][4][4];
    #pragma unroll
    for (int i = 0; i < 4; i++)
        #pragma unroll
        for (int j = 0; j < 4; j++)
            #pragma unroll
            for (int r = 0; r < 4; r++) acc[i][j][r] = 0.0f;

    #pragma unroll 1
    for (int c = 0; c < NC; c++) {
        mbar_wait(smem_u32(&bar_full[c % 3]), (c / 3) & 1);

        const uint32_t sb = sbase + (c % 3) * STAGE;
        #pragma unroll
        for (int kk = 0; kk < 2; kk++) {
            const uint32_t ca = cA[kk];
            uint32_t ah[4][4], al[4][4];
            #pragma unroll
            for (int mi = 0; mi < 4; mi++) {
                LDSM4(ah[mi], sb + offA + mi * 1024 + ca);
                LDSM4(al[mi], sb + 8192 + offA + mi * 1024 + ca);
            }
            #pragma unroll
            for (int p = 0; p < 2; p++) {
                uint32_t bh4[4], bl4[4];
                LDSM4(bh4, sb + 16384 + addrB[p][kk]);
                LDSM4(bl4, sb + 24576 + addrB[p][kk]);
                #pragma unroll
                for (int h = 0; h < 2; h++) {
                    const int ni = 2 * p + h;
                    #pragma unroll
                    for (int mi = 0; mi < 4; mi++) MMA16816(acc[mi][ni], ah[mi], &bh4[2 * h]);
                    #pragma unroll
                    for (int mi = 0; mi < 4; mi++) MMA16816(acc[mi][ni], al[mi], &bh4[2 * h]);
                    #pragma unroll
                    for (int mi = 0; mi < 4; mi++) MMA16816(acc[mi][ni], ah[mi], &bl4[2 * h]);
                }
            }
        }
        if (lane == 0) mbar_arrive(smem_u32(&bar_empty[c % 3]));

        if (tid == 0 && c + 2 < NC) {
            int j = c + 2;
            int s = j % 3;
            if (j >= 3) mbar_wait(smem_u32(&bar_empty[s]), (j / 3 - 1) & 1);
            uint32_t fb = smem_u32(&bar_full[s]);
            mbar_expect(fb, STAGE);
            uint32_t d = sbase + s * STAGE;
            bulk_g2s(d,         Ah + (size_t)j * 8192, 8192, fb);
            bulk_g2s(d + 8192,  Al + (size_t)j * 8192, 8192, fb);
            bulk_g2s(d + 16384, Bh + (size_t)j * 8192, 8192, fb);
            bulk_g2s(d + 24576, Bl + (size_t)j * 8192, 8192, fb);
        }
    }

    __syncthreads();

    if (MODE == 0) {
        const uint32_t chi = sbase, clo = sbase + 32768;
        #pragma unroll
        for (int mi = 0; mi < 4; mi++) {
            #pragma unroll
            for (int ni = 0; ni < 4; ni++) {
                const int nl = wn + ni * 8 + 2 * (lane & 3);
                const int rl = wm + mi * 16 + (lane >> 2);
                float2 bv = *(const float2*)(bias + nb * 128 + nl);
                float v0 = acc[mi][ni][0] + bv.x;
                float v1 = acc[mi][ni][1] + bv.y;
                float v2 = acc[mi][ni][2] + bv.x;
                float v3 = acc[mi][ni][3] + bv.y;
                v0 = (v0 >= 0.0f) ? v0 : NEG_SLOPE * v0;
                v1 = (v1 >= 0.0f) ? v1 : NEG_SLOPE * v1;
                v2 = (v2 >= 0.0f) ? v2 : NEG_SLOPE * v2;
                v3 = (v3 >= 0.0f) ? v3 : NEG_SLOPE * v3;
                __half h0, l0, h1, l1, h2, l2, h3, l3;
                split_h(v0, h0, l0); split_h(v1, h1, l1);
                split_h(v2, h2, l2); split_h(v3, h3, l3);
                const uint32_t tb = (uint32_t)(nl >> 5) * 8192;
                const uint32_t off = swz((uint32_t)rl * 64 + (uint32_t)(nl & 31) * 2);
                asm volatile("st.shared.b32 [%0], %1;" :: "r"(chi + tb + off),       "r"(pack_h2(h0, h1)) : "memory");
                asm volatile("st.shared.b32 [%0], %1;" :: "r"(chi + tb + off + 512), "r"(pack_h2(h2, h3)) : "memory");
                asm volatile("st.shared.b32 [%0], %1;" :: "r"(clo + tb + off),       "r"(pack_h2(l0, l1)) : "memory");
                asm volatile("st.shared.b32 [%0], %1;" :: "r"(clo + tb + off + 512), "r"(pack_h2(l2, l3)) : "memory");
            }
        }
        __syncthreads();
        if (tid == 0) {
            asm volatile("fence.proxy.async;" ::: "memory");
            const size_t tbase = (size_t)mb * 32 + (size_t)nb * 4;
            #pragma unroll
            for (int t = 0; t < 4; t++) {
                bulk_s2g((char*)Ohi + (tbase + t) * 8192, chi + t * 8192, 8192);
                bulk_s2g((char*)Olo + (tbase + t) * 8192, clo + t * 8192, 8192);
            }
            asm volatile("cp.async.bulk.commit_group;" ::: "memory");
            asm volatile("cp.async.bulk.wait_group 0;" ::: "memory");
            if (sig) {
                __threadfence();
                atomicAdd(sig, 1);
            }
        }
    } else {
        const uint32_t cf = sbase;
        #pragma unroll
        for (int mi = 0; mi < 4; mi++) {
            #pragma unroll
            for (int ni = 0; ni < 4; ni++) {
                const int nl = wn + ni * 8 + 2 * (lane & 3);
                const int rl = wm + mi * 16 + (lane >> 2);
                float2 bv = *(const float2*)(bias + nb * 128 + nl);
                float2 p0 = make_float2(tanhf(acc[mi][ni][0] + bv.x),
                                        tanhf(acc[mi][ni][1] + bv.y));
                float2 p1 = make_float2(tanhf(acc[mi][ni][2] + bv.x),
                                        tanhf(acc[mi][ni][3] + bv.y));
                uint32_t a0 = cf + (uint32_t)rl * 512 + (uint32_t)nl * 4;
                asm volatile("st.shared.v2.f32 [%0], {%1, %2};"
                             :: "r"(a0), "f"(p0.x), "f"(p0.y) : "memory");
                asm volatile("st.shared.v2.f32 [%0], {%1, %2};"
                             :: "r"(a0 + 8 * 512), "f"(p1.x), "f"(p1.y) : "memory");
            }
        }
        __syncthreads();
        const uint32_t cf_off = cf - smem_u32(dsm);
        #pragma unroll
        for (int p = 0; p < 16; p++) {
            int idx = p * 256 + tid;
            int r = idx >> 5;
            int c4 = idx & 31;
            uint4 v = *(const uint4*)(dsm + cf_off + r * 512 + c4 * 16);
            *(uint4*)(Of + (size_t)(mb * 128 + r) * Ntot + nb * 128 + c4 * 4) = v;
        }
    }
}

// ---------------------------------------------------------------------------
// Mega-kernel: L2 (0..1023), L3 (1024..2047), L4 (2048..2303).
// ---------------------------------------------------------------------------
__global__ __launch_bounds__(256, 2) void mega_kernel(
    const __half* __restrict__ a0h, const __half* __restrict__ a0l,
    const __half* __restrict__ a1h, const __half* __restrict__ a1l,
    const __half* __restrict__ w2h, const __half* __restrict__ w2l,
    const __half* __restrict__ w3h, const __half* __restrict__ w3l,
    const __half* __restrict__ w4h, const __half* __restrict__ w4l,
    const float* __restrict__ b2, const float* __restrict__ b3,
    const float* __restrict__ b4, float* __restrict__ jnt)
{
    extern __shared__ char dsm[];
    const int bid = blockIdx.x;
    if (bid < 1024) {
        const int mb = bid >> 3, nb = bid & 7;
        gemm_tile<0>(a0h, a0l, w2h, w2l, b2,
                     (__half*)a1h, (__half*)a1l, nullptr, 1024, mb, nb,
                     nullptr, 0, &g_cnt2[mb], dsm);
    } else if (bid < 2048) {
        const int b = bid - 1024;
        const int mb = b >> 3, nb = b & 7;
        gemm_tile<0>(a1h, a1l, w3h, w3l, b3,
                     (__half*)a0h, (__half*)a0l, nullptr, 1024, mb, nb,
                     &g_cnt2[mb], 8, &g_cnt3[mb], dsm);
    } else {
        const int b = bid - 2048;
        const int mb = b >> 1, nb = b & 1;
        gemm_tile<1>(a0h, a0l, w4h, w4l, b4,
                     nullptr, nullptr, jnt, 256, mb, nb,
                     &g_cnt3[mb], 8, nullptr, dsm);
    }
}

// ---------------------------------------------------------------------------
// FK chain (validated, separate launch)
// ---------------------------------------------------------------------------
__global__ __launch_bounds__(256) void fk_kernel(
    const float* __restrict__ joints, float* __restrict__ out)
{
    int row = blockIdx.x * blockDim.x + threadIdx.x;
    if (row >= BATCH) return;
    const float4* jq = (const float4*)(joints + (size_t)row * 256);
    float* o = out + (size_t)row * 192;

    float r00 = 1, r01 = 0, r02 = 0;
    float r10 = 0, r11 = 1, r12 = 0;
    float r20 = 0, r21 = 0, r22 = 1;
    float t0 = 0, t1 = 0, t2 = 0;

    #pragma unroll 4
    for (int j = 0; j < 64; j++) {
        float4 q = jq[j];
        float w = q.x, x = q.y, y = q.z, z = q.w;
        float s = 2.0f / (w * w + x * x + y * y + z * z);

        float R00 = 1.0f - s * (y * y + z * z);
        float R01 = s * (x * y - z * w);
        float R02 = s * (x * z + y * w);
        float R10 = s * (x * y + z * w);
        float R11 = 1.0f - s * (x * x + z * z);
        float R12 = s * (y * z - x * w);
        float R20 = s * (x * z - y * w);
        float R21 = s * (y * z + x * w);
        float R22 = 1.0f - s * (x * x + y * y);

        float n00 = r00 * R00 + r01 * R10 + r02 * R20;
        float n01 = r00 * R01 + r01 * R11 + r02 * R21;
        float n02 = r00 * R02 + r01 * R12 + r02 * R22;
        float n10 = r10 * R00 + r11 * R10 + r12 * R20;
        float n11 = r10 * R01 + r11 * R11 + r12 * R21;
        float n12 = r10 * R02 + r11 * R12 + r12 * R22;
        float n20 = r20 * R00 + r21 * R10 + r22 * R20;
        float n21 = r20 * R01 + r21 * R11 + r22 * R21;
        float n22 = r20 * R02 + r21 * R12 + r22 * R22;

        float nt0 = r00 * R01 + r01 * R11 + r02 * R21 + t0;
        float nt1 = r10 * R01 + r11 * R11 + r12 * R21 + t1;
        float nt2 = r20 * R01 + r21 * R11 + r22 * R21 + t2;

        r00 = n00; r01 = n01; r02 = n02;
        r10 = n10; r11 = n11; r12 = n12;
        r20 = n20; r21 = n21; r22 = n22;
        t0 = nt0; t1 = nt1; t2 = nt2;

        o[j * 3 + 0] = t0;
        o[j * 3 + 1] = t1;
        o[j * 3 + 2] = t2;
    }
}

// ---------------------------------------------------------------------------
// Launch — 3 kernels: producers, mega (L2+L3+L4), FK.
// ---------------------------------------------------------------------------
extern "C" void kernel_launch(void* const* d_in, const int* in_sizes, int n_in,
                              void* d_out, int out_size)
{
    const float* x  = (const float*)d_in[0];
    const float* W1 = (const float*)d_in[1];
    const float* b1 = (const float*)d_in[2];
    const float* W2 = (const float*)d_in[3];
    const float* b2 = (const float*)d_in[4];
    const float* W3 = (const float*)d_in[5];
    const float* b3 = (const float*)d_in[6];
    const float* W4 = (const float*)d_in[7];
    const float* b4 = (const float*)d_in[8];
    float* out = (float*)d_out;

    __half *a0h, *a0l, *a1h, *a1l, *w2h, *w2l, *w3h, *w3l, *w4h, *w4l;
    float* jnt;
    cudaGetSymbolAddress((void**)&a0h, g_a0h);
    cudaGetSymbolAddress((void**)&a0l, g_a0l);
    cudaGetSymbolAddress((void**)&a1h, g_a1h);
    cudaGetSymbolAddress((void**)&a1l, g_a1l);
    cudaGetSymbolAddress((void**)&w2h, g_w2h);
    cudaGetSymbolAddress((void**)&w2l, g_w2l);
    cudaGetSymbolAddress((void**)&w3h, g_w3h);
    cudaGetSymbolAddress((void**)&w3l, g_w3l);
    cudaGetSymbolAddress((void**)&w4h, g_w4h);
    cudaGetSymbolAddress((void**)&w4l, g_w4l);
    cudaGetSymbolAddress((void**)&jnt, g_joints);

    const int SMEM = 3 * 32768 + 1024;   // 99328 -> 2 CTAs/SM
    cudaFuncSetAttribute(mega_kernel, cudaFuncAttributeMaxDynamicSharedMemorySize, SMEM);

    // idx 0: producers (layer1 vectorized + wconv x3) + counter reset
    producers_kernel<<<9345, 256>>>(x, W1, b1, W2, W3, W4,
                                    a0h, a0l, w2h, w2l, w3h, w3l, w4h, w4l);
    // idx 1: fused L2+L3+L4 with dependency counters
    mega_kernel<<<2304, 256, SMEM>>>(a0h, a0l, a1h, a1l,
                                     w2h, w2l, w3h, w3l, w4h, w4l,
                                     b2, b3, b4, jnt);
    // idx 2: FK
    fk_kernel<<<BATCH / 256, 256>>>(jnt, out);
}

// round 16
// speedup vs baseline: 1.0427x; 1.0427x over previous
#include <cuda_runtime.h>
#include <cuda_fp16.h>
#include <math.h>
#include <stdint.h>

// ---------------------------------------------------------------------------
// fkopt_net round 16: round-13 GEMM/mega/FK (byte-exact revert of the LDSM4
// experiment) + tile-granular layer-1 producer: one block per 8KB output
// tile, smem-staged, written with 2x bulk S2G (epilogue pattern) instead of
// per-thread scattered swizzled STG.128.
// ---------------------------------------------------------------------------

#define BATCH 16384
#define KDIM  1024
#define NEG_SLOPE 0.01f

__device__ __align__(1024) __half g_a0h[BATCH * KDIM];
__device__ __align__(1024) __half g_a0l[BATCH * KDIM];
__device__ __align__(1024) __half g_a1h[BATCH * KDIM];
__device__ __align__(1024) __half g_a1l[BATCH * KDIM];
__device__ __align__(1024) __half g_w2h[KDIM * KDIM];
__device__ __align__(1024) __half g_w2l[KDIM * KDIM];
__device__ __align__(1024) __half g_w3h[KDIM * KDIM];
__device__ __align__(1024) __half g_w3l[KDIM * KDIM];
__device__ __align__(1024) __half g_w4h[256 * KDIM];
__device__ __align__(1024) __half g_w4l[256 * KDIM];
__device__ __align__(1024) float g_joints[BATCH * 256];
__device__ int g_cnt2[128];
__device__ int g_cnt3[128];

// ---------------- PTX helpers ----------------------------------------------
__device__ __forceinline__ uint32_t smem_u32(const void* p) {
    uint32_t a;
    asm("{ .reg .u64 t; cvta.to.shared.u64 t, %1; cvt.u32.u64 %0, t; }"
        : "=r"(a) : "l"(p));
    return a;
}
__device__ __forceinline__ void mbar_init(uint32_t a, uint32_t c) {
    asm volatile("mbarrier.init.shared.b64 [%0], %1;" :: "r"(a), "r"(c) : "memory");
}
__device__ __forceinline__ void mbar_expect(uint32_t a, uint32_t tx) {
    asm volatile("mbarrier.arrive.expect_tx.shared.b64 _, [%0], %1;"
                 :: "r"(a), "r"(tx) : "memory");
}
__device__ __forceinline__ void mbar_arrive(uint32_t a) {
    asm volatile("mbarrier.arrive.shared.b64 _, [%0];" :: "r"(a) : "memory");
}
__device__ __forceinline__ void mbar_wait(uint32_t a, uint32_t ph) {
    asm volatile(
        "{\n\t.reg .pred P;\n\t"
        "WL_%=:\n\t"
        "mbarrier.try_wait.parity.acquire.cta.shared::cta.b64 P, [%0], %1, 0x989680;\n\t"
        "@P bra.uni WD_%=;\n\t"
        "bra.uni WL_%=;\n\t"
        "WD_%=:\n\t}"
        :: "r"(a), "r"(ph) : "memory");
}
__device__ __forceinline__ void bulk_g2s(uint32_t dst, const void* src,
                                         uint32_t bytes, uint32_t mbar) {
    asm volatile(
        "cp.async.bulk.shared::cluster.global.mbarrier::complete_tx::bytes "
        "[%0], [%1], %2, [%3];"
        :: "r"(dst), "l"(src), "r"(bytes), "r"(mbar) : "memory");
}
__device__ __forceinline__ void bulk_s2g(void* dst, uint32_t src, uint32_t bytes) {
    asm volatile(
        "cp.async.bulk.global.shared::cta.bulk_group [%0], [%1], %2;"
        :: "l"(dst), "r"(src), "r"(bytes) : "memory");
}

#define LDSM4(r, a)                                                              \
    asm volatile("ldmatrix.sync.aligned.m8n8.x4.shared.b16 {%0,%1,%2,%3}, [%4];" \
                 : "=r"((r)[0]), "=r"((r)[1]), "=r"((r)[2]), "=r"((r)[3])        \
                 : "r"(a))
#define LDSM2(r, a)                                                              \
    asm volatile("ldmatrix.sync.aligned.m8n8.x2.shared.b16 {%0,%1}, [%2];"       \
                 : "=r"((r)[0]), "=r"((r)[1]) : "r"(a))
#define MMA16816(d, a, b)                                                        \
    asm volatile("mma.sync.aligned.m16n8k16.row.col.f32.f16.f16.f32 "            \
                 "{%0,%1,%2,%3}, {%4,%5,%6,%7}, {%8,%9}, {%0,%1,%2,%3};"         \
                 : "+f"((d)[0]), "+f"((d)[1]), "+f"((d)[2]), "+f"((d)[3])        \
                 : "r"((a)[0]), "r"((a)[1]), "r"((a)[2]), "r"((a)[3]),           \
                   "r"((b)[0]), "r"((b)[1]))

// tile byte-offset swizzle: off = row*64 + col*2 (32 fp16 cols per row)
__device__ __forceinline__ uint32_t swz(uint32_t off) {
    return off ^ (((off >> 7) & 3u) << 4);
}
__device__ __forceinline__ void split_h(float v, __half& h, __half& l) {
    h = __float2half_rn(v);
    l = __float2half_rn(v - __half2float(h));
}
__device__ __forceinline__ uint32_t pack_h2(__half a, __half b) {
    return ((uint32_t)__half_as_ushort(b) << 16) | (uint32_t)__half_as_ushort(a);
}

// ---------------------------------------------------------------------------
// Producers:
//   blocks [0,4096): layer1, ONE 8KB output tile per block, smem-staged,
//                    written with 2x bulk S2G.
//   blocks [4096,4608) W2, [4608,5120) W3, [5120,5248) W4 (validated wconv),
//   block 5248 zeroes dependency counters.
// ---------------------------------------------------------------------------
__global__ __launch_bounds__(256) void producers_kernel(
    const float* __restrict__ x,  const float* __restrict__ W1,
    const float* __restrict__ b1, const float* __restrict__ W2,
    const float* __restrict__ W3, const float* __restrict__ W4,
    __half* __restrict__ a0h, __half* __restrict__ a0l,
    __half* __restrict__ w2h, __half* __restrict__ w2l,
    __half* __restrict__ w3h, __half* __restrict__ w3l,
    __half* __restrict__ w4h, __half* __restrict__ w4l)
{
    const int b = blockIdx.x;
    const int tid = threadIdx.x;
    if (b == 5248) {
        if (tid < 128) {
            g_cnt2[tid] = 0;
            g_cnt3[tid] = 0;
        }
        return;
    }
    if (b < 4096) {
        // ---- layer1 tile: mt = b>>5 (128 rows), nt = b&31 (32 cols) ----
        __shared__ __align__(16)  float w1s[4][32];      // rows 0..2: W1; 3: b1
        __shared__ __align__(16)  float xs[384];         // 128 rows x 3
        __shared__ __align__(128) uint32_t stage[4096];  // 8KB hi + 8KB lo
        const int mt = b >> 5, nt = b & 31;
        const int m0 = mt * 128, n0c = nt * 32;

        if (tid < 96) {
            ((float4*)xs)[tid] = *(const float4*)(x + (size_t)m0 * 3 + tid * 4);
        } else if (tid < 128) {
            int c = tid - 96;
            w1s[0][c] = __ldg(W1 + n0c + c);
            w1s[1][c] = __ldg(W1 + 1024 + n0c + c);
            w1s[2][c] = __ldg(W1 + 2048 + n0c + c);
            w1s[3][c] = __ldg(b1 + n0c + c);
        }
        __syncthreads();

        const int row = tid >> 1;             // 0..127
        const int c0  = (tid & 1) * 16;       // 0 or 16
        const float x0 = xs[row * 3 + 0];
        const float x1 = xs[row * 3 + 1];
        const float x2 = xs[row * 3 + 2];

        uint32_t hw[8], lw[8];
        #pragma unroll
        for (int p = 0; p < 8; p++) {
            const int c = c0 + 2 * p;
            float v0 = w1s[3][c]     + x0 * w1s[0][c]     + x1 * w1s[1][c]     + x2 * w1s[2][c];
            float v1 = w1s[3][c + 1] + x0 * w1s[0][c + 1] + x1 * w1s[1][c + 1] + x2 * w1s[2][c + 1];
            v0 = (v0 >= 0.0f) ? v0 : NEG_SLOPE * v0;
            v1 = (v1 >= 0.0f) ? v1 : NEG_SLOPE * v1;
            __half h0, l0, h1, l1;
            split_h(v0, h0, l0); split_h(v1, h1, l1);
            hw[p] = pack_h2(h0, h1);
            lw[p] = pack_h2(l0, l1);
        }
        // stage at swizzled offsets (two 16B chunks per thread per buffer)
        const uint32_t base = (uint32_t)row * 64 + (uint32_t)c0 * 2;
        const uint32_t o0 = swz(base), o1 = swz(base + 16);
        char* st = (char*)stage;
        *(uint4*)(st + o0)        = make_uint4(hw[0], hw[1], hw[2], hw[3]);
        *(uint4*)(st + o1)        = make_uint4(hw[4], hw[5], hw[6], hw[7]);
        *(uint4*)(st + 8192 + o0) = make_uint4(lw[0], lw[1], lw[2], lw[3]);
        *(uint4*)(st + 8192 + o1) = make_uint4(lw[4], lw[5], lw[6], lw[7]);
        __syncthreads();
        if (tid == 0) {
            asm volatile("fence.proxy.async;" ::: "memory");
            bulk_s2g((char*)a0h + (size_t)b * 8192, smem_u32(stage), 8192);
            bulk_s2g((char*)a0l + (size_t)b * 8192, smem_u32(stage) + 8192, 8192);
            asm volatile("cp.async.bulk.commit_group;" ::: "memory");
            asm volatile("cp.async.bulk.wait_group 0;" ::: "memory");
        }
    } else {
        // ---- wconv (validated): W[K,N] fp32 -> tiled hi/lo of W^T ----
        const float* W;
        __half *Ohi, *Olo;
        int N, bb;
        if (b < 4608)      { W = W2; Ohi = w2h; Olo = w2l; N = 1024; bb = b - 4096; }
        else if (b < 5120) { W = W3; Ohi = w3h; Olo = w3l; N = 1024; bb = b - 4608; }
        else               { W = W4; Ohi = w4h; Olo = w4l; N = 256;  bb = b - 5120; }
        int idx = bb * 256 + tid;
        int n  = idx % N;
        int k0 = (idx / N) * 8;
        uint32_t hw[4], lw[4];
        #pragma unroll
        for (int p = 0; p < 4; p++) {
            float v0 = __ldg(W + (size_t)(k0 + 2 * p) * N + n);
            float v1 = __ldg(W + (size_t)(k0 + 2 * p + 1) * N + n);
            __half h0, l0, h1, l1;
            split_h(v0, h0, l0); split_h(v1, h1, l1);
            hw[p] = pack_h2(h0, h1);
            lw[p] = pack_h2(l0, l1);
        }
        size_t tile = (size_t)(n >> 7) * 32 + (k0 >> 5);
        uint32_t off = swz((uint32_t)(n & 127) * 64 + (uint32_t)(k0 & 31) * 2);
        *(uint4*)((char*)Ohi + tile * 8192 + off) = make_uint4(hw[0], hw[1], hw[2], hw[3]);
        *(uint4*)((char*)Olo + tile * 8192 + off) = make_uint4(lw[0], lw[1], lw[2], lw[3]);
    }
}

// ---------------------------------------------------------------------------
// One GEMM tile (128x128, K=1024), fp16x3 mma.sync, 3-stage pipeline.
// Byte-exact round-13 form (LDSM2 for B, prefetch after consumer work).
// ---------------------------------------------------------------------------
template <int MODE>
__device__ __forceinline__ void gemm_tile(
    const __half* __restrict__ Ahg, const __half* __restrict__ Alg,
    const __half* __restrict__ Bhg, const __half* __restrict__ Blg,
    const float* __restrict__ bias,
    __half* __restrict__ Ohi, __half* __restrict__ Olo,
    float* __restrict__ Of, int Ntot, int mb, int nb,
    volatile int* wait_cnt, int wait_target, int* sig,
    char* dsm)
{
    constexpr int NC = 32;
    constexpr uint32_t STAGE = 32768;
    __shared__ __align__(8) uint64_t bar_full[3], bar_empty[3];
    const uint32_t sbase = (smem_u32(dsm) + 1023) & ~1023u;

    const int tid = threadIdx.x, lane = tid & 31, wid = tid >> 5;
    const int wm = (wid & 1) * 64;
    const int wn = (wid >> 1) * 32;

    if (tid == 0) {
        for (int s = 0; s < 3; s++) {
            mbar_init(smem_u32(&bar_full[s]), 1);
            mbar_init(smem_u32(&bar_empty[s]), 8);
        }
    }
    __syncthreads();

    const char* Ah = (const char*)Ahg + (size_t)mb * 32 * 8192;
    const char* Al = (const char*)Alg + (size_t)mb * 32 * 8192;
    const char* Bh = (const char*)Bhg + (size_t)nb * 32 * 8192;
    const char* Bl = (const char*)Blg + (size_t)nb * 32 * 8192;

    if (tid == 0) {
        if (wait_cnt) {
            while (*wait_cnt < wait_target) __nanosleep(64);
            __threadfence();
        }
        #pragma unroll
        for (int c = 0; c < 2; c++) {
            uint32_t fb = smem_u32(&bar_full[c]);
            mbar_expect(fb, STAGE);
            uint32_t d = sbase + c * STAGE;
            bulk_g2s(d,         Ah + (size_t)c * 8192, 8192, fb);
            bulk_g2s(d + 8192,  Al + (size_t)c * 8192, 8192, fb);
            bulk_g2s(d + 16384, Bh + (size_t)c * 8192, 8192, fb);
            bulk_g2s(d + 24576, Bl + (size_t)c * 8192, 8192, fb);
        }
    }

    const int rowA = wm + (lane & 15);
    const uint32_t xa = (rowA >> 1) & 3;
    const uint32_t offA = (uint32_t)rowA * 64;
    const uint32_t cA[2] = { (((uint32_t)(lane >> 4) + 0) ^ xa) * 16,
                             (((uint32_t)(lane >> 4) + 2) ^ xa) * 16 };
    const int rowB = wn + (lane & 7);
    const uint32_t xb = (rowB >> 1) & 3;
    const uint32_t offB = (uint32_t)rowB * 64;
    const uint32_t cB[2] = { ((((uint32_t)(lane >> 3) & 1) + 0) ^ xb) * 16,
                             ((((uint32_t)(lane >> 3) & 1) + 2) ^ xb) * 16 };

    float acc[4][4][4];
    #pragma unroll
    for (int i = 0; i < 4; i++)
        #pragma unroll
        for (int j = 0; j < 4; j++)
            #pragma unroll
            for (int r = 0; r < 4; r++) acc[i][j][r] = 0.0f;

    #pragma unroll 1
    for (int c = 0; c < NC; c++) {
        mbar_wait(smem_u32(&bar_full[c % 3]), (c / 3) & 1);

        const uint32_t sb = sbase + (c % 3) * STAGE;
        #pragma unroll
        for (int kk = 0; kk < 2; kk++) {
            const uint32_t ca = cA[kk], cb = cB[kk];
            uint32_t ah[4][4], al[4][4];
            #pragma unroll
            for (int mi = 0; mi < 4; mi++) {
                LDSM4(ah[mi], sb + offA + mi * 1024 + ca);
                LDSM4(al[mi], sb + 8192 + offA + mi * 1024 + ca);
            }
            #pragma unroll
            for (int ni = 0; ni < 4; ni++) {
                uint32_t bh[2], bl[2];
                LDSM2(bh, sb + 16384 + offB + ni * 512 + cb);
                LDSM2(bl, sb + 24576 + offB + ni * 512 + cb);
                #pragma unroll
                for (int mi = 0; mi < 4; mi++) MMA16816(acc[mi][ni], ah[mi], bh);
                #pragma unroll
                for (int mi = 0; mi < 4; mi++) MMA16816(acc[mi][ni], al[mi], bh);
                #pragma unroll
                for (int mi = 0; mi < 4; mi++) MMA16816(acc[mi][ni], ah[mi], bl);
            }
        }
        if (lane == 0) mbar_arrive(smem_u32(&bar_empty[c % 3]));

        if (tid == 0 && c + 2 < NC) {
            int j = c + 2;
            int s = j % 3;
            if (j >= 3) mbar_wait(smem_u32(&bar_empty[s]), (j / 3 - 1) & 1);
            uint32_t fb = smem_u32(&bar_full[s]);
            mbar_expect(fb, STAGE);
            uint32_t d = sbase + s * STAGE;
            bulk_g2s(d,         Ah + (size_t)j * 8192, 8192, fb);
            bulk_g2s(d + 8192,  Al + (size_t)j * 8192, 8192, fb);
            bulk_g2s(d + 16384, Bh + (size_t)j * 8192, 8192, fb);
            bulk_g2s(d + 24576, Bl + (size_t)j * 8192, 8192, fb);
        }
    }

    __syncthreads();

    if (MODE == 0) {
        const uint32_t chi = sbase, clo = sbase + 32768;
        #pragma unroll
        for (int mi = 0; mi < 4; mi++) {
            #pragma unroll
            for (int ni = 0; ni < 4; ni++) {
                const int nl = wn + ni * 8 + 2 * (lane & 3);
                const int rl = wm + mi * 16 + (lane >> 2);
                float2 bv = *(const float2*)(bias + nb * 128 + nl);
                float v0 = acc[mi][ni][0] + bv.x;
                float v1 = acc[mi][ni][1] + bv.y;
                float v2 = acc[mi][ni][2] + bv.x;
                float v3 = acc[mi][ni][3] + bv.y;
                v0 = (v0 >= 0.0f) ? v0 : NEG_SLOPE * v0;
                v1 = (v1 >= 0.0f) ? v1 : NEG_SLOPE * v1;
                v2 = (v2 >= 0.0f) ? v2 : NEG_SLOPE * v2;
                v3 = (v3 >= 0.0f) ? v3 : NEG_SLOPE * v3;
                __half h0, l0, h1, l1, h2, l2, h3, l3;
                split_h(v0, h0, l0); split_h(v1, h1, l1);
                split_h(v2, h2, l2); split_h(v3, h3, l3);
                const uint32_t tb = (uint32_t)(nl >> 5) * 8192;
                const uint32_t off = swz((uint32_t)rl * 64 + (uint32_t)(nl & 31) * 2);
                asm volatile("st.shared.b32 [%0], %1;" :: "r"(chi + tb + off),       "r"(pack_h2(h0, h1)) : "memory");
                asm volatile("st.shared.b32 [%0], %1;" :: "r"(chi + tb + off + 512), "r"(pack_h2(h2, h3)) : "memory");
                asm volatile("st.shared.b32 [%0], %1;" :: "r"(clo + tb + off),       "r"(pack_h2(l0, l1)) : "memory");
                asm volatile("st.shared.b32 [%0], %1;" :: "r"(clo + tb + off + 512), "r"(pack_h2(l2, l3)) : "memory");
            }
        }
        __syncthreads();
        if (tid == 0) {
            asm volatile("fence.proxy.async;" ::: "memory");
            const size_t tbase = (size_t)mb * 32 + (size_t)nb * 4;
            #pragma unroll
            for (int t = 0; t < 4; t++) {
                bulk_s2g((char*)Ohi + (tbase + t) * 8192, chi + t * 8192, 8192);
                bulk_s2g((char*)Olo + (tbase + t) * 8192, clo + t * 8192, 8192);
            }
            asm volatile("cp.async.bulk.commit_group;" ::: "memory");
            asm volatile("cp.async.bulk.wait_group 0;" ::: "memory");
            if (sig) {
                __threadfence();
                atomicAdd(sig, 1);
            }
        }
    } else {
        const uint32_t cf = sbase;
        #pragma unroll
        for (int mi = 0; mi < 4; mi++) {
            #pragma unroll
            for (int ni = 0; ni < 4; ni++) {
                const int nl = wn + ni * 8 + 2 * (lane & 3);
                const int rl = wm + mi * 16 + (lane >> 2);
                float2 bv = *(const float2*)(bias + nb * 128 + nl);
                float2 p0 = make_float2(tanhf(acc[mi][ni][0] + bv.x),
                                        tanhf(acc[mi][ni][1] + bv.y));
                float2 p1 = make_float2(tanhf(acc[mi][ni][2] + bv.x),
                                        tanhf(acc[mi][ni][3] + bv.y));
                uint32_t a0 = cf + (uint32_t)rl * 512 + (uint32_t)nl * 4;
                asm volatile("st.shared.v2.f32 [%0], {%1, %2};"
                             :: "r"(a0), "f"(p0.x), "f"(p0.y) : "memory");
                asm volatile("st.shared.v2.f32 [%0], {%1, %2};"
                             :: "r"(a0 + 8 * 512), "f"(p1.x), "f"(p1.y) : "memory");
            }
        }
        __syncthreads();
        const uint32_t cf_off = cf - smem_u32(dsm);
        #pragma unroll
        for (int p = 0; p < 16; p++) {
            int idx = p * 256 + tid;
            int r = idx >> 5;
            int c4 = idx & 31;
            uint4 v = *(const uint4*)(dsm + cf_off + r * 512 + c4 * 16);
            *(uint4*)(Of + (size_t)(mb * 128 + r) * Ntot + nb * 128 + c4 * 4) = v;
        }
    }
}

// ---------------------------------------------------------------------------
// Mega-kernel: L2 (0..1023), L3 (1024..2047), L4 (2048..2303).
// ---------------------------------------------------------------------------
__global__ __launch_bounds__(256, 2) void mega_kernel(
    const __half* __restrict__ a0h, const __half* __restrict__ a0l,
    const __half* __restrict__ a1h, const __half* __restrict__ a1l,
    const __half* __restrict__ w2h, const __half* __restrict__ w2l,
    const __half* __restrict__ w3h, const __half* __restrict__ w3l,
    const __half* __restrict__ w4h, const __half* __restrict__ w4l,
    const float* __restrict__ b2, const float* __restrict__ b3,
    const float* __restrict__ b4, float* __restrict__ jnt)
{
    extern __shared__ char dsm[];
    const int bid = blockIdx.x;
    if (bid < 1024) {
        const int mb = bid >> 3, nb = bid & 7;
        gemm_tile<0>(a0h, a0l, w2h, w2l, b2,
                     (__half*)a1h, (__half*)a1l, nullptr, 1024, mb, nb,
                     nullptr, 0, &g_cnt2[mb], dsm);
    } else if (bid < 2048) {
        const int b = bid - 1024;
        const int mb = b >> 3, nb = b & 7;
        gemm_tile<0>(a1h, a1l, w3h, w3l, b3,
                     (__half*)a0h, (__half*)a0l, nullptr, 1024, mb, nb,
                     &g_cnt2[mb], 8, &g_cnt3[mb], dsm);
    } else {
        const int b = bid - 2048;
        const int mb = b >> 1, nb = b & 1;
        gemm_tile<1>(a0h, a0l, w4h, w4l, b4,
                     nullptr, nullptr, jnt, 256, mb, nb,
                     &g_cnt3[mb], 8, nullptr, dsm);
    }
}

// ---------------------------------------------------------------------------
// FK chain (validated, separate launch)
// ---------------------------------------------------------------------------
__global__ __launch_bounds__(256) void fk_kernel(
    const float* __restrict__ joints, float* __restrict__ out)
{
    int row = blockIdx.x * blockDim.x + threadIdx.x;
    if (row >= BATCH) return;
    const float4* jq = (const float4*)(joints + (size_t)row * 256);
    float* o = out + (size_t)row * 192;

    float r00 = 1, r01 = 0, r02 = 0;
    float r10 = 0, r11 = 1, r12 = 0;
    float r20 = 0, r21 = 0, r22 = 1;
    float t0 = 0, t1 = 0, t2 = 0;

    #pragma unroll 4
    for (int j = 0; j < 64; j++) {
        float4 q = jq[j];
        float w = q.x, x = q.y, y = q.z, z = q.w;
        float s = 2.0f / (w * w + x * x + y * y + z * z);

        float R00 = 1.0f - s * (y * y + z * z);
        float R01 = s * (x * y - z * w);
        float R02 = s * (x * z + y * w);
        float R10 = s * (x * y + z * w);
        float R11 = 1.0f - s * (x * x + z * z);
        float R12 = s * (y * z - x * w);
        float R20 = s * (x * z - y * w);
        float R21 = s * (y * z + x * w);
        float R22 = 1.0f - s * (x * x + y * y);

        float n00 = r00 * R00 + r01 * R10 + r02 * R20;
        float n01 = r00 * R01 + r01 * R11 + r02 * R21;
        float n02 = r00 * R02 + r01 * R12 + r02 * R22;
        float n10 = r10 * R00 + r11 * R10 + r12 * R20;
        float n11 = r10 * R01 + r11 * R11 + r12 * R21;
        float n12 = r10 * R02 + r11 * R12 + r12 * R22;
        float n20 = r20 * R00 + r21 * R10 + r22 * R20;
        float n21 = r20 * R01 + r21 * R11 + r22 * R21;
        float n22 = r20 * R02 + r21 * R12 + r22 * R22;

        float nt0 = r00 * R01 + r01 * R11 + r02 * R21 + t0;
        float nt1 = r10 * R01 + r11 * R11 + r12 * R21 + t1;
        float nt2 = r20 * R01 + r21 * R11 + r22 * R21 + t2;

        r00 = n00; r01 = n01; r02 = n02;
        r10 = n10; r11 = n11; r12 = n12;
        r20 = n20; r21 = n21; r22 = n22;
        t0 = nt0; t1 = nt1; t2 = nt2;

        o[j * 3 + 0] = t0;
        o[j * 3 + 1] = t1;
        o[j * 3 + 2] = t2;
    }
}

// ---------------------------------------------------------------------------
// Launch — 3 kernels: producers, mega (L2+L3+L4), FK.
// ---------------------------------------------------------------------------
extern "C" void kernel_launch(void* const* d_in, const int* in_sizes, int n_in,
                              void* d_out, int out_size)
{
    const float* x  = (const float*)d_in[0];
    const float* W1 = (const float*)d_in[1];
    const float* b1 = (const float*)d_in[2];
    const float* W2 = (const float*)d_in[3];
    const float* b2 = (const float*)d_in[4];
    const float* W3 = (const float*)d_in[5];
    const float* b3 = (const float*)d_in[6];
    const float* W4 = (const float*)d_in[7];
    const float* b4 = (const float*)d_in[8];
    float* out = (float*)d_out;

    __half *a0h, *a0l, *a1h, *a1l, *w2h, *w2l, *w3h, *w3l, *w4h, *w4l;
    float* jnt;
    cudaGetSymbolAddress((void**)&a0h, g_a0h);
    cudaGetSymbolAddress((void**)&a0l, g_a0l);
    cudaGetSymbolAddress((void**)&a1h, g_a1h);
    cudaGetSymbolAddress((void**)&a1l, g_a1l);
    cudaGetSymbolAddress((void**)&w2h, g_w2h);
    cudaGetSymbolAddress((void**)&w2l, g_w2l);
    cudaGetSymbolAddress((void**)&w3h, g_w3h);
    cudaGetSymbolAddress((void**)&w3l, g_w3l);
    cudaGetSymbolAddress((void**)&w4h, g_w4h);
    cudaGetSymbolAddress((void**)&w4l, g_w4l);
    cudaGetSymbolAddress((void**)&jnt, g_joints);

    const int SMEM = 3 * 32768 + 1024;   // 99328 -> 2 CTAs/SM
    cudaFuncSetAttribute(mega_kernel, cudaFuncAttributeMaxDynamicSharedMemorySize, SMEM);

    // idx 0: producers (tile-granular layer1 + wconv x3) + counter reset
    producers_kernel<<<5249, 256>>>(x, W1, b1, W2, W3, W4,
                                    a0h, a0l, w2h, w2l, w3h, w3l, w4h, w4l);
    // idx 1: fused L2+L3+L4 with dependency counters
    mega_kernel<<<2304, 256, SMEM>>>(a0h, a0l, a1h, a1l,
                                     w2h, w2l, w3h, w3l, w4h, w4l,
                                     b2, b3, b4, jnt);
    // idx 2: FK
    fk_kernel<<<BATCH / 256, 256>>>(jnt, out);
}